// round 16
// baseline (speedup 1.0000x reference)
#include <cuda_runtime.h>
#include <cuda_fp16.h>
#include <math_constants.h>

#define SS 4096
#define II 1024
#define CC 8
#define HH 8
#define SBLK (SS/32)

typedef unsigned long long u64;

// ---- scratch ----
__device__ __half2 g_kw[(size_t)II*SS];       // (k, w=exp(bias)) per [i][s]
__device__ __half  g_vh[(size_t)II*SS];       // v [i][s], fp16
__device__ uint4   g_mn[(size_t)SS*II];       // normalized mn: 8 fp16 per (s,i)
__device__ float   g_qpart[(size_t)SBLK*II*9];
__device__ float   g_o[(size_t)II*HH];

// ---- helpers ----
__device__ __forceinline__ u64 pk2(float lo, float hi){u64 r;asm("mov.b64 %0,{%1,%2};":"=l"(r):"f"(lo),"f"(hi));return r;}
__device__ __forceinline__ void un2(u64 v, float&a, float&b){asm("mov.b64 {%0,%1},%2;":"=f"(a),"=f"(b):"l"(v));}
__device__ __forceinline__ u64 f2fma(u64 a,u64 b,u64 c){u64 d;asm("fma.rn.f32x2 %0,%1,%2,%3;":"=l"(d):"l"(a),"l"(b),"l"(c));return d;}
__device__ __forceinline__ u64 f2add(u64 a,u64 b){u64 d;asm("add.rn.f32x2 %0,%1,%2;":"=l"(d):"l"(a),"l"(b));return d;}
__device__ __forceinline__ u64 f2mul(u64 a,u64 b){u64 d;asm("mul.rn.f32x2 %0,%1,%2;":"=l"(d):"l"(a),"l"(b));return d;}
__device__ __forceinline__ float tanha(float x){float r;asm("tanh.approx.f32 %0,%1;":"=f"(r):"f"(x));return r;}

// ============================================================
// K1: LayerNorm + (k,w)/v planes (transposed) + mn (fp16, [s][i])
//     + q-pool partials.  512 threads x 2 rows/thread: natural
//     live set ~63 regs -> 2 CTAs/SM = 32 warps (50% occ).
// grid (II/32, SS/32), block 512
// ============================================================
__global__ __launch_bounds__(512,2) void k1_kernel(
    const float* __restrict__ m, const float* __restrict__ mask,
    const float* __restrict__ gamma, const float* __restrict__ beta,
    const float* __restrict__ Wk, const float* __restrict__ Wv)
{
    __shared__ float tk[32][33], tv[32][33], tw[32][33];
    __shared__ float red2[16][32*9 + 4];
    __shared__ float wgt[32];
    int tid = threadIdx.x;
    if (tid < 32) {
        float v;
        if      (tid <  8) v = gamma[tid];
        else if (tid < 16) v = beta[tid-8];
        else if (tid < 24) v = Wk[tid-16];
        else               v = Wv[tid-24];
        wgt[tid] = v;
    }
    __syncthreads();

    int il = tid & 31, wp = tid >> 5;        // wp 0..15
    int i  = blockIdx.x*32 + il;
    int s0 = blockIdx.y*32;
    int sb = s0 + wp*2;

    // front-batched streaming m loads (never re-read: .cs)
    float4 A[2][2];
    #pragma unroll
    for (int r = 0; r < 2; r++) {
        const float4* p = reinterpret_cast<const float4*>(m + ((size_t)(sb+r)*II + i)*CC);
        A[r][0] = __ldcs(p); A[r][1] = __ldcs(p+1);
    }

    float qacc[8];
    #pragma unroll
    for (int c = 0; c < 8; c++) qacc[c] = 0.f;
    float macc = 0.f;

    #pragma unroll
    for (int r = 0; r < 2; r++) {
        int sl = wp*2 + r;
        float mk = __ldcs(&mask[(size_t)(sb+r)*II + i]);
        const float* x = &A[r][0].x;     // 8 contiguous floats
        float mu = 0.f;
        #pragma unroll
        for (int c = 0; c < 8; c++) mu += x[c];
        mu *= 0.125f;
        float var = 0.f;
        #pragma unroll
        for (int c = 0; c < 8; c++) { float d = x[c]-mu; var += d*d; }
        var *= 0.125f;
        float rstd = rsqrtf(var + 1e-5f);
        float kv = 0.f, vv = 0.f;
        unsigned gp[4];
        float prev;
        #pragma unroll
        for (int c = 0; c < 8; c++) {
            float mn = (x[c]-mu)*rstd*wgt[c] + wgt[8+c];
            kv += mn*wgt[16+c];
            vv += mn*wgt[24+c];
            qacc[c] += mn*mk;
            if (c & 1) {
                __half2 hh = __floats2half2_rn(prev, mn);
                gp[c>>1] = *reinterpret_cast<unsigned*>(&hh);
            } else prev = mn;
        }
        macc += mk;
        tk[il][sl] = kv;
        tv[il][sl] = vv;
        tw[il][sl] = __expf(1e9f*(mk - 1.f));
        g_mn[(size_t)(sb+r)*II + i] = make_uint4(gp[0], gp[1], gp[2], gp[3]);
    }
    __syncthreads();

    // coalesced transposed writeout (first 256 threads, as before)
    if (tid < 256) {
        int ir = tid >> 3, sj = (tid & 7)*4;
        size_t off = (size_t)(blockIdx.x*32 + ir)*SS + s0 + sj;
        __half2 v0 = __floats2half2_rn(tv[ir][sj],   tv[ir][sj+1]);
        __half2 v1 = __floats2half2_rn(tv[ir][sj+2], tv[ir][sj+3]);
        uint2 uv;
        uv.x = *reinterpret_cast<unsigned int*>(&v0);
        uv.y = *reinterpret_cast<unsigned int*>(&v1);
        *reinterpret_cast<uint2*>(g_vh + off) = uv;
        __half2 h0 = __floats2half2_rn(tk[ir][sj],   tw[ir][sj]);
        __half2 h1 = __floats2half2_rn(tk[ir][sj+1], tw[ir][sj+1]);
        __half2 h2 = __floats2half2_rn(tk[ir][sj+2], tw[ir][sj+2]);
        __half2 h3 = __floats2half2_rn(tk[ir][sj+3], tw[ir][sj+3]);
        uint4 u;
        u.x = *reinterpret_cast<unsigned int*>(&h0);
        u.y = *reinterpret_cast<unsigned int*>(&h1);
        u.z = *reinterpret_cast<unsigned int*>(&h2);
        u.w = *reinterpret_cast<unsigned int*>(&h3);
        *reinterpret_cast<uint4*>(g_kw + off) = u;
    }

    // single-round q-pool reduction: 16 warp partials -> 3 warps finish
    #pragma unroll
    for (int c = 0; c < 8; c++) red2[wp][il*9 + c] = qacc[c];
    red2[wp][il*9 + 8] = macc;
    __syncthreads();
    if (wp < 3) {
        #pragma unroll
        for (int j = 0; j < 3; j++) {
            int c = wp*3 + j;
            float sum = 0.f;
            #pragma unroll
            for (int w = 0; w < 16; w++) sum += red2[w][il*9 + c];
            g_qpart[((size_t)blockIdx.y*II + i)*9 + c] = sum;
        }
    }
}

// ---------------- block reduction ----------------
__device__ __forceinline__ float warp_sum(float v) {
    #pragma unroll
    for (int o = 16; o; o >>= 1) v += __shfl_xor_sync(0xffffffffu, v, o);
    return v;
}
template<int N>
__device__ __forceinline__ void block_sum(float* vals, float* buf) {
    int lane = threadIdx.x & 31, wp = threadIdx.x >> 5;
    __syncthreads();
    #pragma unroll
    for (int n = 0; n < N; n++) {
        float v = warp_sum(vals[n]);
        if (lane == 0) buf[wp*N + n] = v;
    }
    __syncthreads();
    if (threadIdx.x < N) {
        float r = buf[threadIdx.x];
        #pragma unroll
        for (int w = 1; w < 8; w++) r += buf[w*N + threadIdx.x];
        buf[8*N + threadIdx.x] = r;
    }
    __syncthreads();
    #pragma unroll
    for (int n = 0; n < N; n++) vals[n] = buf[8*N + n];
}

// ============================================================
// K2: per-column q + softmax over s (coalesced chunk ownership).
// ============================================================
__global__ __launch_bounds__(256) void k2_kernel(const float* __restrict__ Wq)
{
    __shared__ float buf[9*16];
    __shared__ float swq[64];
    int tid = threadIdx.x;
    int i = blockIdx.x;
    if (tid < 64) swq[tid] = Wq[tid];

    float part[9];
    #pragma unroll
    for (int c = 0; c < 9; c++) part[c] = 0.f;
    if (tid < SBLK) {
        const float* p = g_qpart + ((size_t)tid*II + i)*9;
        #pragma unroll
        for (int c = 0; c < 9; c++) part[c] = __ldcs(p + c);
    }
    block_sum<9>(part, buf);

    float inv = 1.f/(part[8] + 1e-5f);
    float q[8];
    #pragma unroll
    for (int h = 0; h < 8; h++) {
        float s = 0.f;
        #pragma unroll
        for (int c = 0; c < 8; c++) s += (part[c]*inv)*swq[c*8 + h];
        q[h] = s;
    }

    const uint4* kwrow = reinterpret_cast<const uint4*>(g_kw + (size_t)i*SS);
    const uint2* vrow  = reinterpret_cast<const uint2*>(g_vh + (size_t)i*SS);
    uint4 kw4[4];
    uint2 v2[4];
    #pragma unroll
    for (int g = 0; g < 4; g++) kw4[g] = __ldcs(kwrow + g*256 + tid);
    #pragma unroll
    for (int g = 0; g < 4; g++) v2[g]  = __ldcs(vrow  + g*256 + tid);

    float so[16];
    #pragma unroll
    for (int n = 0; n < 16; n++) so[n] = 0.f;

    #pragma unroll
    for (int g = 0; g < 4; g++) {
        unsigned kwu[4] = {kw4[g].x, kw4[g].y, kw4[g].z, kw4[g].w};
        unsigned vu[2]  = {v2[g].x, v2[g].y};
        float vvf[4];
        {
            float2 f0 = __half22float2(*reinterpret_cast<__half2*>(&vu[0]));
            float2 f1 = __half22float2(*reinterpret_cast<__half2*>(&vu[1]));
            vvf[0] = f0.x; vvf[1] = f0.y; vvf[2] = f1.x; vvf[3] = f1.y;
        }
        #pragma unroll
        for (int e = 0; e < 4; e++) {
            float2 kw = __half22float2(*reinterpret_cast<__half2*>(&kwu[e]));
            float kk = kw.x, w = kw.y;
            float vE = vvf[e];
            #pragma unroll
            for (int h = 0; h < 8; h++) {
                float ex = w * __expf(q[h]*kk);
                so[h]   += ex;
                so[8+h] = fmaf(ex, vE, so[8+h]);
            }
        }
    }
    block_sum<16>(so, buf);

    if (tid < 8) g_o[(size_t)i*8 + tid] = so[8+tid] / so[tid];
}

// ============================================================
// K3: gate = sigmoid(mn@Wg+bg) from fp16 mn, out = (oh.*g)@Wo+bo.
// p-outer, 4 rows/thread, no launch cap (verified-best config).
// grid (II/32, SS/32), block 256
// ============================================================
__global__ __launch_bounds__(256) void k3_kernel(
    const float* __restrict__ Wg, const float* __restrict__ bg,
    const float* __restrict__ Wo, const float* __restrict__ bo,
    float* __restrict__ out)
{
    __shared__ ulonglong2 sWG[8][4];   // [h][cpair]: dup 0.5*Wg[c][h]
    __shared__ u64 sCB[8];             // dup 0.5*bg[h]
    __shared__ ulonglong2 sWO[8][4];   // [h][cpair]: dup Wo[h][c]
    __shared__ u64 sBO[8];             // dup bo[c]

    int tid = threadIdx.x;
    if (tid < 32) {
        int h = tid >> 2, cp = tid & 3;
        float w0 = 0.5f*Wg[(2*cp)*8 + h];
        float w1 = 0.5f*Wg[(2*cp+1)*8 + h];
        sWG[h][cp] = make_ulonglong2(pk2(w0,w0), pk2(w1,w1));
    } else if (tid < 64) {
        int t = tid - 32; int h = t >> 2, cp = t & 3;
        float w0 = Wo[h*8 + 2*cp], w1 = Wo[h*8 + 2*cp+1];
        sWO[h][cp] = make_ulonglong2(pk2(w0,w0), pk2(w1,w1));
    } else if (tid < 72) {
        int h = tid - 64;
        float c = 0.5f*bg[h];
        sCB[h] = pk2(c, c);
    } else if (tid < 80) {
        int c = tid - 72;
        sBO[c] = pk2(bo[c], bo[c]);
    }

    int il = tid & 31, wp = tid >> 5;
    int i  = blockIdx.x*32 + il;
    int s0 = (gridDim.y - 1 - blockIdx.y)*32;   // tail-first: ride K1's L2 tail
    int sb = s0 + wp*4;

    float oh2[8];   // 0.5*oh
    {
        const float4* po = reinterpret_cast<const float4*>(g_o + (size_t)i*8);
        float4 a = po[0], b4 = po[1];
        oh2[0]=0.5f*a.x; oh2[1]=0.5f*a.y; oh2[2]=0.5f*a.z; oh2[3]=0.5f*a.w;
        oh2[4]=0.5f*b4.x; oh2[5]=0.5f*b4.y; oh2[6]=0.5f*b4.z; oh2[7]=0.5f*b4.w;
    }

    uint4 G[4];
    #pragma unroll
    for (int r = 0; r < 4; r++) G[r] = g_mn[(size_t)(sb+r)*II + i];
    __syncthreads();

    #pragma unroll
    for (int p = 0; p < 2; p++) {
        u64 xp[8];
        {
            unsigned ua[4] = {G[2*p].x, G[2*p].y, G[2*p].z, G[2*p].w};
            unsigned ub[4] = {G[2*p+1].x, G[2*p+1].y, G[2*p+1].z, G[2*p+1].w};
            #pragma unroll
            for (int j = 0; j < 4; j++) {
                float2 fa = __half22float2(*reinterpret_cast<__half2*>(&ua[j]));
                float2 fb = __half22float2(*reinterpret_cast<__half2*>(&ub[j]));
                xp[2*j]   = pk2(fa.x, fb.x);
                xp[2*j+1] = pk2(fa.y, fb.y);
            }
        }

        u64 acc[8];
        #pragma unroll
        for (int c = 0; c < 8; c++) acc[c] = sBO[c];

        #pragma unroll
        for (int h = 0; h < 8; h++) {
            ulonglong2 w0 = sWG[h][0], w1 = sWG[h][1], w2 = sWG[h][2], w3 = sWG[h][3];
            u64 dot = f2mul(xp[0], w0.x);
            dot = f2fma(xp[1], w0.y, dot);
            dot = f2fma(xp[2], w1.x, dot);
            dot = f2fma(xp[3], w1.y, dot);
            dot = f2fma(xp[4], w2.x, dot);
            dot = f2fma(xp[5], w2.y, dot);
            dot = f2fma(xp[6], w3.x, dot);
            dot = f2fma(xp[7], w3.y, dot);
            u64 z2 = f2add(dot, sCB[h]);                // 0.5*z
            float za, zb; un2(z2, za, zb);
            float t0 = fmaf(oh2[h], tanha(za), oh2[h]); // oh*sigmoid(z)
            float t1 = fmaf(oh2[h], tanha(zb), oh2[h]);
            u64 th = pk2(t0, t1);
            ulonglong2 o0 = sWO[h][0], o1 = sWO[h][1], o2 = sWO[h][2], o3 = sWO[h][3];
            acc[0] = f2fma(th, o0.x, acc[0]);
            acc[1] = f2fma(th, o0.y, acc[1]);
            acc[2] = f2fma(th, o1.x, acc[2]);
            acc[3] = f2fma(th, o1.y, acc[3]);
            acc[4] = f2fma(th, o2.x, acc[4]);
            acc[5] = f2fma(th, o2.y, acc[5]);
            acc[6] = f2fma(th, o3.x, acc[6]);
            acc[7] = f2fma(th, o3.y, acc[7]);
        }

        float y0[8], y1[8];
        #pragma unroll
        for (int c = 0; c < 8; c++) un2(acc[c], y0[c], y1[c]);
        size_t off0 = ((size_t)(sb+2*p)*II + i)*CC;
        size_t off1 = ((size_t)(sb+2*p+1)*II + i)*CC;
        __stcs(reinterpret_cast<float4*>(out + off0),     make_float4(y0[0],y0[1],y0[2],y0[3]));
        __stcs(reinterpret_cast<float4*>(out + off0 + 4), make_float4(y0[4],y0[5],y0[6],y0[7]));
        __stcs(reinterpret_cast<float4*>(out + off1),     make_float4(y1[0],y1[1],y1[2],y1[3]));
        __stcs(reinterpret_cast<float4*>(out + off1 + 4), make_float4(y1[4],y1[5],y1[6],y1[7]));
    }
}

// ============================================================
extern "C" void kernel_launch(void* const* d_in, const int* in_sizes, int n_in,
                              void* d_out, int out_size)
{
    const float* m     = (const float*)d_in[0];
    const float* mask  = (const float*)d_in[1];
    const float* gamma = (const float*)d_in[2];
    const float* beta  = (const float*)d_in[3];
    const float* Wq    = (const float*)d_in[4];
    const float* Wk    = (const float*)d_in[5];
    const float* Wv    = (const float*)d_in[6];
    const float* Wg    = (const float*)d_in[7];
    const float* bg    = (const float*)d_in[8];
    const float* Wo    = (const float*)d_in[9];
    const float* bo    = (const float*)d_in[10];
    float* out = (float*)d_out;

    dim3 g1(II/32, SS/32);
    k1_kernel<<<g1, 512>>>(m, mask, gamma, beta, Wk, Wv);
    k2_kernel<<<II, 256>>>(Wq);
    dim3 g3(II/32, SS/32);
    k3_kernel<<<g3, 256>>>(Wg, bg, Wo, bo, out);
}

// round 17
// speedup vs baseline: 1.0810x; 1.0810x over previous
#include <cuda_runtime.h>
#include <cuda_fp16.h>
#include <math_constants.h>

#define SS 4096
#define II 1024
#define CC 8
#define HH 8
#define SBLK (SS/32)

typedef unsigned long long u64;

// ---- scratch ----
__device__ __half2 g_kw[(size_t)II*SS];       // (k, w=exp(bias)) per [i][s]
__device__ __half  g_vh[(size_t)II*SS];       // v [i][s], fp16
__device__ uint4   g_mn[(size_t)SS*II];       // normalized mn: 8 fp16 per (s,i)
__device__ float   g_qpart[(size_t)SBLK*II*9];
__device__ float   g_o[(size_t)II*HH];

// ---- helpers ----
__device__ __forceinline__ u64 pk2(float lo, float hi){u64 r;asm("mov.b64 %0,{%1,%2};":"=l"(r):"f"(lo),"f"(hi));return r;}
__device__ __forceinline__ void un2(u64 v, float&a, float&b){asm("mov.b64 {%0,%1},%2;":"=f"(a),"=f"(b):"l"(v));}
__device__ __forceinline__ u64 f2fma(u64 a,u64 b,u64 c){u64 d;asm("fma.rn.f32x2 %0,%1,%2,%3;":"=l"(d):"l"(a),"l"(b),"l"(c));return d;}
__device__ __forceinline__ u64 f2add(u64 a,u64 b){u64 d;asm("add.rn.f32x2 %0,%1,%2;":"=l"(d):"l"(a),"l"(b));return d;}
__device__ __forceinline__ u64 f2mul(u64 a,u64 b){u64 d;asm("mul.rn.f32x2 %0,%1,%2;":"=l"(d):"l"(a),"l"(b));return d;}
__device__ __forceinline__ float tanha(float x){float r;asm("tanh.approx.f32 %0,%1;":"=f"(r):"f"(x));return r;}

// ============================================================
// K1: LayerNorm + (k,w)/v planes (transposed) + mn (fp16, [s][i])
//     + q-pool partials.  m AND mask loads front-batched (MLP 12).
// grid (II/32, SS/32), block 256
// ============================================================
__global__ __launch_bounds__(256,3) void k1_kernel(
    const float* __restrict__ m, const float* __restrict__ mask,
    const float* __restrict__ gamma, const float* __restrict__ beta,
    const float* __restrict__ Wk, const float* __restrict__ Wv)
{
    __shared__ float tk[32][33], tv[32][33], tw[32][33];
    __shared__ float red2[8][32*9 + 4];
    __shared__ float wgt[32];
    int tid = threadIdx.x;
    if (tid < 32) {
        float v;
        if      (tid <  8) v = gamma[tid];
        else if (tid < 16) v = beta[tid-8];
        else if (tid < 24) v = Wk[tid-16];
        else               v = Wv[tid-24];
        wgt[tid] = v;
    }
    __syncthreads();

    int il = tid & 31, wp = tid >> 5;
    int i  = blockIdx.x*32 + il;
    int s0 = blockIdx.y*32;
    int sb = s0 + wp*4;

    // front-batched streaming loads: 8 LDG.128 + 4 mask LDG.32 in flight
    float4 A[4][2];
    float mk[4];
    #pragma unroll
    for (int r = 0; r < 4; r++) {
        const float4* p = reinterpret_cast<const float4*>(m + ((size_t)(sb+r)*II + i)*CC);
        A[r][0] = __ldcs(p); A[r][1] = __ldcs(p+1);
    }
    #pragma unroll
    for (int r = 0; r < 4; r++) mk[r] = __ldcs(&mask[(size_t)(sb+r)*II + i]);

    float qacc[8];
    #pragma unroll
    for (int c = 0; c < 8; c++) qacc[c] = 0.f;
    float macc = 0.f;

    #pragma unroll
    for (int r = 0; r < 4; r++) {
        int sl = wp*4 + r;
        const float* x = &A[r][0].x;     // 8 contiguous floats
        float mu = 0.f;
        #pragma unroll
        for (int c = 0; c < 8; c++) mu += x[c];
        mu *= 0.125f;
        float var = 0.f;
        #pragma unroll
        for (int c = 0; c < 8; c++) { float d = x[c]-mu; var += d*d; }
        var *= 0.125f;
        float rstd = rsqrtf(var + 1e-5f);
        float kv = 0.f, vv = 0.f;
        unsigned gp[4];
        float prev;
        #pragma unroll
        for (int c = 0; c < 8; c++) {
            float mn = (x[c]-mu)*rstd*wgt[c] + wgt[8+c];
            kv += mn*wgt[16+c];
            vv += mn*wgt[24+c];
            qacc[c] += mn*mk[r];
            if (c & 1) {
                __half2 hh = __floats2half2_rn(prev, mn);
                gp[c>>1] = *reinterpret_cast<unsigned*>(&hh);
            } else prev = mn;
        }
        macc += mk[r];
        tk[il][sl] = kv;
        tv[il][sl] = vv;
        tw[il][sl] = __expf(1e9f*(mk[r] - 1.f));
        g_mn[(size_t)(sb+r)*II + i] = make_uint4(gp[0], gp[1], gp[2], gp[3]);
    }
    __syncthreads();

    // coalesced transposed writeout (scratch stays L2-resident for K2)
    {
        int ir = tid >> 3, sj = (tid & 7)*4;
        size_t off = (size_t)(blockIdx.x*32 + ir)*SS + s0 + sj;
        __half2 v0 = __floats2half2_rn(tv[ir][sj],   tv[ir][sj+1]);
        __half2 v1 = __floats2half2_rn(tv[ir][sj+2], tv[ir][sj+3]);
        uint2 uv;
        uv.x = *reinterpret_cast<unsigned int*>(&v0);
        uv.y = *reinterpret_cast<unsigned int*>(&v1);
        *reinterpret_cast<uint2*>(g_vh + off) = uv;
        __half2 h0 = __floats2half2_rn(tk[ir][sj],   tw[ir][sj]);
        __half2 h1 = __floats2half2_rn(tk[ir][sj+1], tw[ir][sj+1]);
        __half2 h2 = __floats2half2_rn(tk[ir][sj+2], tw[ir][sj+2]);
        __half2 h3 = __floats2half2_rn(tk[ir][sj+3], tw[ir][sj+3]);
        uint4 u;
        u.x = *reinterpret_cast<unsigned int*>(&h0);
        u.y = *reinterpret_cast<unsigned int*>(&h1);
        u.z = *reinterpret_cast<unsigned int*>(&h2);
        u.w = *reinterpret_cast<unsigned int*>(&h3);
        *reinterpret_cast<uint4*>(g_kw + off) = u;
    }

    // single-round q-pool reduction: warp partials -> 3 warps finish
    #pragma unroll
    for (int c = 0; c < 8; c++) red2[wp][il*9 + c] = qacc[c];
    red2[wp][il*9 + 8] = macc;
    __syncthreads();
    if (wp < 3) {
        #pragma unroll
        for (int j = 0; j < 3; j++) {
            int c = wp*3 + j;
            float sum = 0.f;
            #pragma unroll
            for (int w = 0; w < 8; w++) sum += red2[w][il*9 + c];
            g_qpart[((size_t)blockIdx.y*II + i)*9 + c] = sum;
        }
    }
}

// ---------------- block reduction ----------------
__device__ __forceinline__ float warp_sum(float v) {
    #pragma unroll
    for (int o = 16; o; o >>= 1) v += __shfl_xor_sync(0xffffffffu, v, o);
    return v;
}
template<int N>
__device__ __forceinline__ void block_sum(float* vals, float* buf) {
    int lane = threadIdx.x & 31, wp = threadIdx.x >> 5;
    __syncthreads();
    #pragma unroll
    for (int n = 0; n < N; n++) {
        float v = warp_sum(vals[n]);
        if (lane == 0) buf[wp*N + n] = v;
    }
    __syncthreads();
    if (threadIdx.x < N) {
        float r = buf[threadIdx.x];
        #pragma unroll
        for (int w = 1; w < 8; w++) r += buf[w*N + threadIdx.x];
        buf[8*N + threadIdx.x] = r;
    }
    __syncthreads();
    #pragma unroll
    for (int n = 0; n < N; n++) vals[n] = buf[8*N + n];
}

// ============================================================
// K2: per-column q + softmax over s (coalesced chunk ownership).
// ============================================================
__global__ __launch_bounds__(256) void k2_kernel(const float* __restrict__ Wq)
{
    __shared__ float buf[9*16];
    __shared__ float swq[64];
    int tid = threadIdx.x;
    int i = blockIdx.x;
    if (tid < 64) swq[tid] = Wq[tid];

    float part[9];
    #pragma unroll
    for (int c = 0; c < 9; c++) part[c] = 0.f;
    if (tid < SBLK) {
        const float* p = g_qpart + ((size_t)tid*II + i)*9;
        #pragma unroll
        for (int c = 0; c < 9; c++) part[c] = __ldcs(p + c);
    }
    block_sum<9>(part, buf);

    float inv = 1.f/(part[8] + 1e-5f);
    float q[8];
    #pragma unroll
    for (int h = 0; h < 8; h++) {
        float s = 0.f;
        #pragma unroll
        for (int c = 0; c < 8; c++) s += (part[c]*inv)*swq[c*8 + h];
        q[h] = s;
    }

    const uint4* kwrow = reinterpret_cast<const uint4*>(g_kw + (size_t)i*SS);
    const uint2* vrow  = reinterpret_cast<const uint2*>(g_vh + (size_t)i*SS);
    uint4 kw4[4];
    uint2 v2[4];
    #pragma unroll
    for (int g = 0; g < 4; g++) kw4[g] = __ldcs(kwrow + g*256 + tid);
    #pragma unroll
    for (int g = 0; g < 4; g++) v2[g]  = __ldcs(vrow  + g*256 + tid);

    float so[16];
    #pragma unroll
    for (int n = 0; n < 16; n++) so[n] = 0.f;

    #pragma unroll
    for (int g = 0; g < 4; g++) {
        unsigned kwu[4] = {kw4[g].x, kw4[g].y, kw4[g].z, kw4[g].w};
        unsigned vu[2]  = {v2[g].x, v2[g].y};
        float vvf[4];
        {
            float2 f0 = __half22float2(*reinterpret_cast<__half2*>(&vu[0]));
            float2 f1 = __half22float2(*reinterpret_cast<__half2*>(&vu[1]));
            vvf[0] = f0.x; vvf[1] = f0.y; vvf[2] = f1.x; vvf[3] = f1.y;
        }
        #pragma unroll
        for (int e = 0; e < 4; e++) {
            float2 kw = __half22float2(*reinterpret_cast<__half2*>(&kwu[e]));
            float kk = kw.x, w = kw.y;
            float vE = vvf[e];
            #pragma unroll
            for (int h = 0; h < 8; h++) {
                float ex = w * __expf(q[h]*kk);
                so[h]   += ex;
                so[8+h] = fmaf(ex, vE, so[8+h]);
            }
        }
    }
    block_sum<16>(so, buf);

    if (tid < 8) g_o[(size_t)i*8 + tid] = so[8+tid] / so[tid];
}

// ============================================================
// K3: gate = sigmoid(mn@Wg+bg) from fp16 mn, out = (oh.*g)@Wo+bo.
// p-outer, 4 rows/thread, no launch cap (verified-best config).
// grid (II/32, SS/32), block 256
// ============================================================
__global__ __launch_bounds__(256) void k3_kernel(
    const float* __restrict__ Wg, const float* __restrict__ bg,
    const float* __restrict__ Wo, const float* __restrict__ bo,
    float* __restrict__ out)
{
    __shared__ ulonglong2 sWG[8][4];   // [h][cpair]: dup 0.5*Wg[c][h]
    __shared__ u64 sCB[8];             // dup 0.5*bg[h]
    __shared__ ulonglong2 sWO[8][4];   // [h][cpair]: dup Wo[h][c]
    __shared__ u64 sBO[8];             // dup bo[c]

    int tid = threadIdx.x;
    if (tid < 32) {
        int h = tid >> 2, cp = tid & 3;
        float w0 = 0.5f*Wg[(2*cp)*8 + h];
        float w1 = 0.5f*Wg[(2*cp+1)*8 + h];
        sWG[h][cp] = make_ulonglong2(pk2(w0,w0), pk2(w1,w1));
    } else if (tid < 64) {
        int t = tid - 32; int h = t >> 2, cp = t & 3;
        float w0 = Wo[h*8 + 2*cp], w1 = Wo[h*8 + 2*cp+1];
        sWO[h][cp] = make_ulonglong2(pk2(w0,w0), pk2(w1,w1));
    } else if (tid < 72) {
        int h = tid - 64;
        float c = 0.5f*bg[h];
        sCB[h] = pk2(c, c);
    } else if (tid < 80) {
        int c = tid - 72;
        sBO[c] = pk2(bo[c], bo[c]);
    }

    int il = tid & 31, wp = tid >> 5;
    int i  = blockIdx.x*32 + il;
    int s0 = (gridDim.y - 1 - blockIdx.y)*32;   // tail-first: ride K1's L2 tail
    int sb = s0 + wp*4;

    float oh2[8];   // 0.5*oh
    {
        const float4* po = reinterpret_cast<const float4*>(g_o + (size_t)i*8);
        float4 a = po[0], b4 = po[1];
        oh2[0]=0.5f*a.x; oh2[1]=0.5f*a.y; oh2[2]=0.5f*a.z; oh2[3]=0.5f*a.w;
        oh2[4]=0.5f*b4.x; oh2[5]=0.5f*b4.y; oh2[6]=0.5f*b4.z; oh2[7]=0.5f*b4.w;
    }

    uint4 G[4];
    #pragma unroll
    for (int r = 0; r < 4; r++) G[r] = g_mn[(size_t)(sb+r)*II + i];
    __syncthreads();

    #pragma unroll
    for (int p = 0; p < 2; p++) {
        u64 xp[8];
        {
            unsigned ua[4] = {G[2*p].x, G[2*p].y, G[2*p].z, G[2*p].w};
            unsigned ub[4] = {G[2*p+1].x, G[2*p+1].y, G[2*p+1].z, G[2*p+1].w};
            #pragma unroll
            for (int j = 0; j < 4; j++) {
                float2 fa = __half22float2(*reinterpret_cast<__half2*>(&ua[j]));
                float2 fb = __half22float2(*reinterpret_cast<__half2*>(&ub[j]));
                xp[2*j]   = pk2(fa.x, fb.x);
                xp[2*j+1] = pk2(fa.y, fb.y);
            }
        }

        u64 acc[8];
        #pragma unroll
        for (int c = 0; c < 8; c++) acc[c] = sBO[c];

        #pragma unroll
        for (int h = 0; h < 8; h++) {
            ulonglong2 w0 = sWG[h][0], w1 = sWG[h][1], w2 = sWG[h][2], w3 = sWG[h][3];
            u64 dot = f2mul(xp[0], w0.x);
            dot = f2fma(xp[1], w0.y, dot);
            dot = f2fma(xp[2], w1.x, dot);
            dot = f2fma(xp[3], w1.y, dot);
            dot = f2fma(xp[4], w2.x, dot);
            dot = f2fma(xp[5], w2.y, dot);
            dot = f2fma(xp[6], w3.x, dot);
            dot = f2fma(xp[7], w3.y, dot);
            u64 z2 = f2add(dot, sCB[h]);                // 0.5*z
            float za, zb; un2(z2, za, zb);
            float t0 = fmaf(oh2[h], tanha(za), oh2[h]); // oh*sigmoid(z)
            float t1 = fmaf(oh2[h], tanha(zb), oh2[h]);
            u64 th = pk2(t0, t1);
            ulonglong2 o0 = sWO[h][0], o1 = sWO[h][1], o2 = sWO[h][2], o3 = sWO[h][3];
            acc[0] = f2fma(th, o0.x, acc[0]);
            acc[1] = f2fma(th, o0.y, acc[1]);
            acc[2] = f2fma(th, o1.x, acc[2]);
            acc[3] = f2fma(th, o1.y, acc[3]);
            acc[4] = f2fma(th, o2.x, acc[4]);
            acc[5] = f2fma(th, o2.y, acc[5]);
            acc[6] = f2fma(th, o3.x, acc[6]);
            acc[7] = f2fma(th, o3.y, acc[7]);
        }

        float y0[8], y1[8];
        #pragma unroll
        for (int c = 0; c < 8; c++) un2(acc[c], y0[c], y1[c]);
        size_t off0 = ((size_t)(sb+2*p)*II + i)*CC;
        size_t off1 = ((size_t)(sb+2*p+1)*II + i)*CC;
        __stcs(reinterpret_cast<float4*>(out + off0),     make_float4(y0[0],y0[1],y0[2],y0[3]));
        __stcs(reinterpret_cast<float4*>(out + off0 + 4), make_float4(y0[4],y0[5],y0[6],y0[7]));
        __stcs(reinterpret_cast<float4*>(out + off1),     make_float4(y1[0],y1[1],y1[2],y1[3]));
        __stcs(reinterpret_cast<float4*>(out + off1 + 4), make_float4(y1[4],y1[5],y1[6],y1[7]));
    }
}

// ============================================================
extern "C" void kernel_launch(void* const* d_in, const int* in_sizes, int n_in,
                              void* d_out, int out_size)
{
    const float* m     = (const float*)d_in[0];
    const float* mask  = (const float*)d_in[1];
    const float* gamma = (const float*)d_in[2];
    const float* beta  = (const float*)d_in[3];
    const float* Wq    = (const float*)d_in[4];
    const float* Wk    = (const float*)d_in[5];
    const float* Wv    = (const float*)d_in[6];
    const float* Wg    = (const float*)d_in[7];
    const float* bg    = (const float*)d_in[8];
    const float* Wo    = (const float*)d_in[9];
    const float* bo    = (const float*)d_in[10];
    float* out = (float*)d_out;

    dim3 g1(II/32, SS/32);
    k1_kernel<<<g1, 256>>>(m, mask, gamma, beta, Wk, Wv);
    k2_kernel<<<II, 256>>>(Wq);
    dim3 g3(II/32, SS/32);
    k3_kernel<<<g3, 256>>>(Wg, bg, Wo, bo, out);
}